// round 9
// baseline (speedup 1.0000x reference)
#include <cuda_runtime.h>
#include <cuda_fp16.h>
#include <cstdint>

#define VOCAB 30000
#define VROWS 30080          // padded row count for partial-norm slabs
#define DIN   512
#define DH    1024
#define DOUT  2047
#define DOUTP 2048
#define NB    4096
#define SEQ   20
#define NSLAB 64             // 16 N-tiles x 4 wn warps

// ---------------- scratch (__device__ globals; allocation-free rule) ----------------
__device__ __half g_H1f[(size_t)VOCAB * DIN];      // fp16
__device__ __half g_W2T[(size_t)DH * DIN];         // [1024,512] N-major fp16
__device__ __half g_W3T[(size_t)DOUTP * DH];       // [2048,1024] fp16, row 2047 zero
__device__ __half g_H2f[(size_t)VOCAB * DH];       // fp16
__device__ __half g_Eh[(size_t)VOCAB * DOUTP];     // fp16 E, padded col 2047 == 0
__device__ float  g_nsq[(size_t)NSLAB * VROWS];    // per-slab partial sum-of-squares (fp32)
__device__ float  g_invnorm[VOCAB];

// ---------------- PTX helpers (generic PTX only; valid at compute_103) ----------------
static __device__ __forceinline__ uint32_t smem_to_u32(const void* p) {
    uint32_t a;
    asm("{ .reg .u64 t; cvta.to.shared.u64 t, %1; cvt.u32.u64 %0, t; }" : "=r"(a) : "l"(p));
    return a;
}
#define CP16(dst, src) \
    asm volatile("cp.async.cg.shared.global [%0], [%1], 16;" :: "r"(dst), "l"(src) : "memory")
#define CP_COMMIT() asm volatile("cp.async.commit_group;" ::: "memory")
#define CP_WAIT4()  asm volatile("cp.async.wait_group 4;" ::: "memory")

#define LDSM4(r0, r1, r2, r3, addr) \
    asm volatile("ldmatrix.sync.aligned.m8n8.x4.shared.b16 {%0,%1,%2,%3}, [%4];" \
        : "=r"(r0), "=r"(r1), "=r"(r2), "=r"(r3) : "r"(addr))

#define MMA_F16(d, a0, a1, a2, a3, b0, b1) \
    asm volatile("mma.sync.aligned.m16n8k16.row.col.f32.f16.f16.f32 " \
        "{%0,%1,%2,%3},{%4,%5,%6,%7},{%8,%9},{%0,%1,%2,%3};" \
        : "+f"((d)[0]), "+f"((d)[1]), "+f"((d)[2]), "+f"((d)[3]) \
        : "r"(a0), "r"(a1), "r"(a2), "r"(a3), "r"(b0), "r"(b1))

// swizzled byte offset inside a 128-row x 64-byte tile (8KB): 4 chunks of 16B per row
static __device__ __forceinline__ uint32_t sw_off(int row, int ch) {
    return (uint32_t)(row * 64 + ((ch ^ ((row >> 1) & 3)) << 4));
}
static __device__ __forceinline__ uint32_t pack_h2(float x, float y) {
    __half2 h = __floats2half2_rn(x, y);
    return *reinterpret_cast<uint32_t*>(&h);
}

// ---------------- prep kernels ----------------
__global__ __launch_bounds__(256) void prep_h1(const float* __restrict__ W1,
                                               const float* __restrict__ b1) {
    size_t i4 = ((size_t)blockIdx.x * 256 + threadIdx.x) * 4;
    if (i4 >= (size_t)VOCAB * DIN) return;
    int k = (int)(i4 % DIN);
    float4 w  = *reinterpret_cast<const float4*>(&W1[i4]);
    float4 bb = *reinterpret_cast<const float4*>(&b1[k]);
    __half h[4] = { __float2half_rn(fmaxf(w.x + bb.x, 0.f)),
                    __float2half_rn(fmaxf(w.y + bb.y, 0.f)),
                    __float2half_rn(fmaxf(w.z + bb.z, 0.f)),
                    __float2half_rn(fmaxf(w.w + bb.w, 0.f)) };
    *reinterpret_cast<uint2*>(&g_H1f[i4]) = *reinterpret_cast<uint2*>(h);
}

// src [K][N] row-major fp32 -> dst [NP][K] fp16 (rows n>=N zero). Tiled transpose.
__global__ __launch_bounds__(256) void transpose_f16(const float* __restrict__ src,
                                                     __half* __restrict__ dst,
                                                     int K, int N) {
    __shared__ float tile[32][33];
    const int tx = threadIdx.x & 31, ty = threadIdx.x >> 5;   // 32 x 8
    const int n0 = blockIdx.x * 32, k0 = blockIdx.y * 32;
#pragma unroll
    for (int i = 0; i < 4; ++i) {
        int k = k0 + ty + i * 8, n = n0 + tx;
        tile[ty + i * 8][tx] = (n < N) ? src[(size_t)k * N + n] : 0.f;
    }
    __syncthreads();
#pragma unroll
    for (int i = 0; i < 4; ++i) {
        int n = n0 + ty + i * 8, k = k0 + tx;
        dst[(size_t)n * K + k] = __float2half_rn(tile[tx][ty + i * 8]);
    }
}

// ---------------- HMMA fp16 GEMM (deep cp.async pipeline) ----------------
// C = act(A @ B^T + bias), fp16 in, fp16 out. CTA tile 128x128, K-chunk 32,
// 6-stage cp.async pipeline (A|B @ 8KB each = 16KB/stage), wait_group 4.
static constexpr int STAGE_BYTES = 16384;
static constexpr int NSTAGE      = 6;
static constexpr int GEMM_SMEM   = NSTAGE * STAGE_BYTES;   // 96 KB

template <bool WITH_NSQ>   // true: no relu + write norm partials; false: relu
__global__ __launch_bounds__(256, 2)
void hmma_gemm(const __half* __restrict__ Af, const __half* __restrict__ Bf,
               const float* __restrict__ bias,
               __half* __restrict__ C,
               int M, int K, int ldc, int nbias)
{
    extern __shared__ __align__(128) uint8_t smem[];
    const uint32_t sbase = smem_to_u32(smem);
    const int tid  = threadIdx.x;
    const int lane = tid & 31;
    const int wid  = tid >> 5;
    const int wm   = wid >> 2;          // 0..1  (m block of 64)
    const int wn   = wid & 3;           // 0..3  (n block of 32)
    const int m0   = blockIdx.y * 128;
    const int n0   = blockIdx.x * 128;

    const int lmat  = lane >> 3;
    const int lrow8 = ((lmat & 1) << 3) + (lane & 7);
    const int lchb  = lmat >> 1;        // 16B chunk parity within a k16

    float acc[4][4][4];
#pragma unroll
    for (int a = 0; a < 4; ++a)
#pragma unroll
        for (int b = 0; b < 4; ++b)
#pragma unroll
            for (int c = 0; c < 4; ++c) acc[a][b][c] = 0.f;

    auto load_stage = [&](int s, int k0) {
        const uint32_t base = sbase + s * STAGE_BYTES;
#pragma unroll
        for (int p = 0; p < 2; ++p) {
            int idx = p * 256 + tid;            // 0..511
            int row = idx >> 2;                 // 0..127
            int ch  = idx & 3;                  // 16B chunk in 64B row
            uint32_t doff = sw_off(row, ch);
            int gm = m0 + row; if (gm > M - 1) gm = M - 1;   // clamp; rows >= M never stored
            CP16(base +        doff, Af + (size_t)gm * K + k0 + ch * 8);
            CP16(base + 8192 + doff, Bf + (size_t)(n0 + row) * K + k0 + ch * 8);
        }
        CP_COMMIT();
    };

    // one K32 chunk: B frags for both k16 halves loaded early; A just-in-time
    auto compute_chunk = [&](uint32_t base) {
        uint32_t b0[2][4], b1[2][4], af[4][4];
        const int ch0 = lchb, ch1 = 2 + lchb;
#pragma unroll
        for (int np = 0; np < 2; ++np) {
            uint32_t addr = base + 8192 + sw_off(wn * 32 + np * 16 + lrow8, ch0);
            LDSM4(b0[np][0], b0[np][1], b0[np][2], b0[np][3], addr);
        }
#pragma unroll
        for (int mt = 0; mt < 4; ++mt) {
            uint32_t addr = base + sw_off(wm * 64 + mt * 16 + lrow8, ch0);
            LDSM4(af[mt][0], af[mt][1], af[mt][2], af[mt][3], addr);
        }
#pragma unroll
        for (int np = 0; np < 2; ++np) {
            uint32_t addr = base + 8192 + sw_off(wn * 32 + np * 16 + lrow8, ch1);
            LDSM4(b1[np][0], b1[np][1], b1[np][2], b1[np][3], addr);
        }
#pragma unroll
        for (int mt = 0; mt < 4; ++mt)
#pragma unroll
            for (int np = 0; np < 2; ++np)
#pragma unroll
                for (int ni = 0; ni < 2; ++ni)
                    MMA_F16(acc[mt][np * 2 + ni],
                            af[mt][0], af[mt][1], af[mt][2], af[mt][3],
                            b0[np][ni], b0[np][ni + 2]);
#pragma unroll
        for (int mt = 0; mt < 4; ++mt) {
            uint32_t addr = base + sw_off(wm * 64 + mt * 16 + lrow8, ch1);
            LDSM4(af[mt][0], af[mt][1], af[mt][2], af[mt][3], addr);
        }
#pragma unroll
        for (int mt = 0; mt < 4; ++mt)
#pragma unroll
            for (int np = 0; np < 2; ++np)
#pragma unroll
                for (int ni = 0; ni < 2; ++ni)
                    MMA_F16(acc[mt][np * 2 + ni],
                            af[mt][0], af[mt][1], af[mt][2], af[mt][3],
                            b1[np][ni], b1[np][ni + 2]);
    };

    const int T = K >> 5;                 // GEMM1: 16, GEMM2: 32  (always > NSTAGE)
#pragma unroll
    for (int s = 0; s < 5; ++s) load_stage(s, s * 32);
    CP_WAIT4();
    __syncthreads();                      // stage 0 resident

    int cs = 0, ls = 5;                   // current slot, load slot (rotating, no %)
    for (int t = 0; t < T; ++t) {
        if (t + 5 < T) load_stage(ls, (t + 5) << 5);
        else           CP_COMMIT();       // keep group count aligned for wait_group 4
        compute_chunk(sbase + cs * STAGE_BYTES);
        if (t + 1 < T) {
            CP_WAIT4();
            __syncthreads();              // stage t+1 resident
        }
        if (++cs == NSTAGE) cs = 0;
        if (++ls == NSTAGE) ls = 0;
    }

    // ---------------- epilogue ----------------
    const int mbase = m0 + wm * 64 + (lane >> 2);
    const int nbase = n0 + wn * 32 + (lane & 3) * 2;
#pragma unroll
    for (int mt = 0; mt < 4; ++mt) {
        int m = mbase + mt * 16;
        float s0 = 0.f, s1 = 0.f;
#pragma unroll
        for (int nt = 0; nt < 4; ++nt) {
            int n = nbase + nt * 8;
            float b0 = (n     < nbias) ? __ldg(&bias[n])     : 0.f;
            float b1 = (n + 1 < nbias) ? __ldg(&bias[n + 1]) : 0.f;
            float v00 = acc[mt][nt][0] + b0, v01 = acc[mt][nt][1] + b1;
            float v10 = acc[mt][nt][2] + b0, v11 = acc[mt][nt][3] + b1;
            if (WITH_NSQ) {
                s0 += v00 * v00 + v01 * v01;
                s1 += v10 * v10 + v11 * v11;
            } else {
                v00 = fmaxf(v00, 0.f); v01 = fmaxf(v01, 0.f);
                v10 = fmaxf(v10, 0.f); v11 = fmaxf(v11, 0.f);
            }
            if (m < M)
                *reinterpret_cast<uint32_t*>(&C[(size_t)m * ldc + n]) = pack_h2(v00, v01);
            if (m + 8 < M)
                *reinterpret_cast<uint32_t*>(&C[(size_t)(m + 8) * ldc + n]) = pack_h2(v10, v11);
        }
        if (WITH_NSQ) {
            s0 += __shfl_xor_sync(0xffffffffu, s0, 1);
            s0 += __shfl_xor_sync(0xffffffffu, s0, 2);
            s1 += __shfl_xor_sync(0xffffffffu, s1, 1);
            s1 += __shfl_xor_sync(0xffffffffu, s1, 2);
            if ((lane & 3) == 0) {
                size_t slab = (size_t)(blockIdx.x * 4 + wn) * VROWS;
                if (m < M)     g_nsq[slab + m]     = s0;
                if (m + 8 < M) g_nsq[slab + m + 8] = s1;
            }
        }
    }
}

// ---------------- norm finalize + gather ----------------
__global__ __launch_bounds__(256) void rsqrt_kernel() {
    int r = blockIdx.x * 256 + threadIdx.x;
    if (r >= VOCAB) return;
    float tot = 0.f;
#pragma unroll
    for (int s = 0; s < NSLAB; ++s) tot += g_nsq[(size_t)s * VROWS + r];
    g_invnorm[r] = 1.f / fmaxf(sqrtf(tot), 1e-12f);
}

// out[b] = sum_{l<len} Eh[id] * invnorm[id]; each thread owns 8 consecutive cols.
// NOTE: out rows have stride 2047 floats -> NOT 16B aligned for odd b; scalar stores only.
__global__ __launch_bounds__(256) void gather_kernel(const int* __restrict__ ingrs,
                                                     const int* __restrict__ lengths,
                                                     float* __restrict__ out) {
    __shared__ const uint4* sptr[SEQ];
    __shared__ float sscl[SEQ];
    const int b = blockIdx.x;
    const int t = threadIdx.x;
    if (t < SEQ) {
        int id = ingrs[b * SEQ + t];
        sptr[t] = reinterpret_cast<const uint4*>(&g_Eh[(size_t)id * DOUTP]);
        sscl[t] = g_invnorm[id];
    }
    __syncthreads();
    int len = lengths[b];
    if (len > SEQ) len = SEQ;

    float acc[8] = {0.f,0.f,0.f,0.f,0.f,0.f,0.f,0.f};
    for (int l = 0; l < len; ++l) {
        const float s = sscl[l];
        uint4 v = __ldg(&sptr[l][t]);           // 8 halves, 16B-aligned (row stride 4KB)
        const __half2* h = reinterpret_cast<const __half2*>(&v);
#pragma unroll
        for (int q = 0; q < 4; ++q) {
            float2 f = __half22float2(h[q]);
            acc[q * 2]     += f.x * s;
            acc[q * 2 + 1] += f.y * s;
        }
    }
    float* o = out + (size_t)b * DOUT;
    const int c0 = t * 8;
    const int lim = DOUT - c0;                  // last thread writes 7
#pragma unroll
    for (int j = 0; j < 8; ++j)
        if (j < lim) o[c0 + j] = acc[j];
}

// ---------------- launch ----------------
extern "C" void kernel_launch(void* const* d_in, const int* in_sizes, int n_in,
                              void* d_out, int out_size)
{
    const int*   ingrs   = (const int*)  d_in[0];
    const int*   lengths = (const int*)  d_in[1];
    const float* W1      = (const float*)d_in[2];
    const float* b1      = (const float*)d_in[3];
    const float* W2      = (const float*)d_in[4];
    const float* b2      = (const float*)d_in[5];
    const float* W3      = (const float*)d_in[6];
    const float* b3      = (const float*)d_in[7];
    float* out = (float*)d_out;

    __half *h1f, *w2t, *w3t, *h2f, *eh;
    cudaGetSymbolAddress((void**)&h1f, g_H1f);
    cudaGetSymbolAddress((void**)&w2t, g_W2T);
    cudaGetSymbolAddress((void**)&w3t, g_W3T);
    cudaGetSymbolAddress((void**)&h2f, g_H2f);
    cudaGetSymbolAddress((void**)&eh,  g_Eh);

    cudaFuncSetAttribute(hmma_gemm<true>,  cudaFuncAttributeMaxDynamicSharedMemorySize, GEMM_SMEM);
    cudaFuncSetAttribute(hmma_gemm<false>, cudaFuncAttributeMaxDynamicSharedMemorySize, GEMM_SMEM);

    prep_h1<<<(VOCAB * DIN / 4 + 255) / 256, 256>>>(W1, b1);
    transpose_f16<<<dim3(DH / 32, DIN / 32), 256>>>(W2, w2t, DIN, DH);
    transpose_f16<<<dim3(DOUTP / 32, DH / 32), 256>>>(W3, w3t, DH, DOUT);

    // GEMM1: H2 = relu(H1 @ W2^T + b2)   [30000,1024] fp16
    dim3 g1(DH / 128, (VOCAB + 127) / 128);
    hmma_gemm<false><<<g1, 256, GEMM_SMEM>>>(h1f, w2t, b2, h2f, VOCAB, DIN, DH, DH);

    // GEMM2: E = H2 @ W3^T + b3          [30000,2048 padded] fp16 + fp32 norm partials
    dim3 g2(DOUTP / 128, (VOCAB + 127) / 128);
    hmma_gemm<true><<<g2, 256, GEMM_SMEM>>>(h2f, w3t, b3, eh, VOCAB, DH, DOUTP, DOUT);

    rsqrt_kernel<<<(VOCAB + 255) / 256, 256>>>();
    gather_kernel<<<NB, 256>>>(ingrs, lengths, out);
}